// round 9
// baseline (speedup 1.0000x reference)
#include <cuda_runtime.h>
#include <cuda_bf16.h>

// Problem constants (fixed by the dataset)
#define BB   4
#define NN   4096
#define EE   1024
#define HH   16
#define DD   64
#define KK   256
#define RR   32
#define MM   (BB * NN)        // 16384 rows

// ---------------------------------------------------------------------------
// Scratch (device globals; no allocation allowed)
// ---------------------------------------------------------------------------
__device__ float g_t1[MM * RR];          // x @ qU^T           (16384, 32)
__device__ float g_k [MM * DD];          // x @ kW^T           (16384, 64)
__device__ float g_t2[MM * (EE / 2)];    // t1 @ qV^T          (16384, 512)
__device__ float g_q [MM * EE];          // t2 @ qW^T + qb     (16384, 1024)
__device__ float g_kv[BB * KK * DD];     // kv                 (4, 256, 64)
__device__ float g_at[MM * EE];          // attention output   (16384, 1024)

// ---------------------------------------------------------------------------
// Generic SGEMM (NT): C[M,N] = A[M,Kd] * B[N,Kd]^T (+ bias[n])
// BM=128, BK=8, TM=8; BN/TN templated (covers N = 32, 64, >=128).
// Requires: M % 128 == 0, N % BN == 0, Kd % 8 == 0 (true for all our shapes).
// ---------------------------------------------------------------------------
template<int BN, int TN>
__global__ __launch_bounds__(256)
void sgemm_nt(const float* __restrict__ A, const float* __restrict__ B,
              const float* __restrict__ bias, float* __restrict__ C,
              int M, int N, int Kd)
{
    constexpr int BM = 128, BK = 8, TM = 8;
    __shared__ float As[BK][BM];
    __shared__ float Bs[BK][BN];

    const int tid = threadIdx.x;
    const int ty  = tid >> 4;    // 0..15  -> rows ty*8..+8
    const int tx  = tid & 15;    // 0..15  -> cols tx*TN..+TN
    const int m0  = blockIdx.y * BM;
    const int n0  = blockIdx.x * BN;

    float acc[TM][TN];
#pragma unroll
    for (int i = 0; i < TM; i++)
#pragma unroll
        for (int j = 0; j < TN; j++) acc[i][j] = 0.f;

    const int nK = Kd / BK;
    for (int kt = 0; kt < nK; kt++) {
        const int k0 = kt * BK;
        // A tile: 128 rows x 8 k = 256 float4, one per thread (transposed store)
        {
            const int row = tid >> 1;
            const int kq  = (tid & 1) * 4;
            float4 v = *(const float4*)(A + (size_t)(m0 + row) * Kd + k0 + kq);
            As[kq + 0][row] = v.x; As[kq + 1][row] = v.y;
            As[kq + 2][row] = v.z; As[kq + 3][row] = v.w;
        }
        // B tile: BN rows x 8 k = BN*2 float4
        for (int i = tid; i < BN * 2; i += 256) {
            const int col = i >> 1;
            const int kq  = (i & 1) * 4;
            float4 v = *(const float4*)(B + (size_t)(n0 + col) * Kd + k0 + kq);
            Bs[kq + 0][col] = v.x; Bs[kq + 1][col] = v.y;
            Bs[kq + 2][col] = v.z; Bs[kq + 3][col] = v.w;
        }
        __syncthreads();

#pragma unroll
        for (int kk = 0; kk < BK; kk++) {
            float a[TM], b[TN];
#pragma unroll
            for (int i = 0; i < TM; i++) a[i] = As[kk][ty * TM + i];
#pragma unroll
            for (int j = 0; j < TN; j++) b[j] = Bs[kk][tx * TN + j];
#pragma unroll
            for (int i = 0; i < TM; i++)
#pragma unroll
                for (int j = 0; j < TN; j++)
                    acc[i][j] = fmaf(a[i], b[j], acc[i][j]);
        }
        __syncthreads();
    }

#pragma unroll
    for (int i = 0; i < TM; i++) {
        const int r = m0 + ty * TM + i;
#pragma unroll
        for (int j = 0; j < TN; j++) {
            const int c = n0 + tx * TN + j;
            float v = acc[i][j];
            if (bias) v += bias[c];
            C[(size_t)r * N + c] = v;
        }
    }
}

// ---------------------------------------------------------------------------
// kv[b,kidx,d] = sum_n  k[b,n,d] * key_proj[n,kidx]
// grid (KK/4, BB), block 256: 4 kidx per block, 64 d lanes each.
// ---------------------------------------------------------------------------
__global__ __launch_bounds__(256)
void kv_kernel(const float* __restrict__ kmat, const float* __restrict__ kp,
               float* __restrict__ kv)
{
    const int b    = blockIdx.y;
    const int kidx = blockIdx.x * 4 + (threadIdx.x >> 6);
    const int d    = threadIdx.x & 63;
    const float* kb = kmat + (size_t)b * NN * DD;

    float acc = 0.f;
#pragma unroll 4
    for (int n = 0; n < NN; n++)
        acc = fmaf(kb[n * DD + d], __ldg(&kp[n * KK + kidx]), acc);

    kv[((b << 8) + kidx) * DD + d] = acc;
}

// ---------------------------------------------------------------------------
// Fused attention: per block one (b,h) and a 64-row tile of n.
//   S = Q(64x64) @ KV^T (64x256)  [regs, 8x8/lane]
//   softmax over k (warp shuffles; each warp owns 8 rows, k = tx + 32j)
//   O = P(64x256) @ KV (64x64)    [P staged in smem]
// smem: KV[256][66] + Q[64][66] + P[64][260] = 151,040 B (dynamic).
// ---------------------------------------------------------------------------
#define LDK 66
#define LDP 260
#define ATTN_SMEM ((KK * LDK + 64 * LDK + 64 * LDP) * (int)sizeof(float))

__global__ __launch_bounds__(256, 1)
void attn_kernel(const float* __restrict__ q, const float* __restrict__ kv,
                 float* __restrict__ out)
{
    extern __shared__ float sm[];
    float* KVs = sm;                    // [256][66]
    float* Qs  = KVs + KK * LDK;        // [64][66]
    float* Ps  = Qs + 64 * LDK;         // [64][260]

    const int bh = blockIdx.y;
    const int b  = bh / HH;
    const int h  = bh % HH;
    const int n0 = blockIdx.x * 64;
    const int tid = threadIdx.x;

    // load KV[b] (256x64)
    for (int i = tid; i < KK * DD; i += 256) {
        const int k = i >> 6, d = i & 63;
        KVs[k * LDK + d] = kv[((b << 8) + k) * DD + d];
    }
    // load Q tile (64 rows x 64 d), head h
    for (int i = tid; i < 64 * DD; i += 256) {
        const int r = i >> 6, d = i & 63;
        Qs[r * LDK + d] = q[(size_t)(b * NN + n0 + r) * EE + h * DD + d];
    }
    __syncthreads();

    const int ty = tid >> 5;   // warp id: rows ty*8..+8
    const int tx = tid & 31;   // lane: k = tx + 32*j

    // ---- S = Q @ KV^T ----
    float acc[8][8];
#pragma unroll
    for (int i = 0; i < 8; i++)
#pragma unroll
        for (int j = 0; j < 8; j++) acc[i][j] = 0.f;

    for (int d = 0; d < DD; d++) {
        float qa[8], kb[8];
#pragma unroll
        for (int i = 0; i < 8; i++) qa[i] = Qs[(ty * 8 + i) * LDK + d];   // broadcast
#pragma unroll
        for (int j = 0; j < 8; j++) kb[j] = KVs[(tx + 32 * j) * LDK + d];
#pragma unroll
        for (int i = 0; i < 8; i++)
#pragma unroll
            for (int j = 0; j < 8; j++)
                acc[i][j] = fmaf(qa[i], kb[j], acc[i][j]);
    }

    // ---- softmax over k (scale = D^-0.5 = 0.125) ----
    const float scale = 0.125f;
#pragma unroll
    for (int i = 0; i < 8; i++) {
        float m = acc[i][0];
#pragma unroll
        for (int j = 1; j < 8; j++) m = fmaxf(m, acc[i][j]);
#pragma unroll
        for (int off = 16; off; off >>= 1)
            m = fmaxf(m, __shfl_xor_sync(0xffffffffu, m, off));
        float s = 0.f;
#pragma unroll
        for (int j = 0; j < 8; j++) {
            acc[i][j] = __expf((acc[i][j] - m) * scale);
            s += acc[i][j];
        }
#pragma unroll
        for (int off = 16; off; off >>= 1)
            s += __shfl_xor_sync(0xffffffffu, s, off);
        const float inv = __fdividef(1.f, s);
#pragma unroll
        for (int j = 0; j < 8; j++)
            Ps[(ty * 8 + i) * LDP + tx + 32 * j] = acc[i][j] * inv;
    }
    __syncthreads();

    // ---- O = P @ KV ---- (lane handles d = tx*2, tx*2+1)
    float o[8][2];
#pragma unroll
    for (int i = 0; i < 8; i++) { o[i][0] = 0.f; o[i][1] = 0.f; }

    for (int k = 0; k < KK; k++) {
        const float2 v = *(const float2*)&KVs[k * LDK + tx * 2];   // LDK even -> 8B aligned
#pragma unroll
        for (int i = 0; i < 8; i++) {
            const float p = Ps[(ty * 8 + i) * LDP + k];            // broadcast
            o[i][0] = fmaf(p, v.x, o[i][0]);
            o[i][1] = fmaf(p, v.y, o[i][1]);
        }
    }

#pragma unroll
    for (int i = 0; i < 8; i++) {
        const size_t base = (size_t)(b * NN + n0 + ty * 8 + i) * EE + h * DD + tx * 2;
        out[base + 0] = o[i][0];
        out[base + 1] = o[i][1];
    }
}

// ---------------------------------------------------------------------------
// Launch
// ---------------------------------------------------------------------------
extern "C" void kernel_launch(void* const* d_in, const int* in_sizes, int n_in,
                              void* d_out, int out_size)
{
    const float* x  = (const float*)d_in[0];
    const float* qU = (const float*)d_in[1];
    const float* qV = (const float*)d_in[2];
    const float* qW = (const float*)d_in[3];
    const float* qb = (const float*)d_in[4];
    const float* kW = (const float*)d_in[5];
    const float* kp = (const float*)d_in[6];
    const float* oW = (const float*)d_in[7];
    const float* ob = (const float*)d_in[8];
    float* out = (float*)d_out;

    float *t1, *kk, *t2, *q, *kv, *attn;
    cudaGetSymbolAddress((void**)&t1,   g_t1);
    cudaGetSymbolAddress((void**)&kk,   g_k);
    cudaGetSymbolAddress((void**)&t2,   g_t2);
    cudaGetSymbolAddress((void**)&q,    g_q);
    cudaGetSymbolAddress((void**)&kv,   g_kv);
    cudaGetSymbolAddress((void**)&attn, g_at);

    cudaFuncSetAttribute(attn_kernel,
                         cudaFuncAttributeMaxDynamicSharedMemorySize, ATTN_SMEM);

    const dim3 blk(256);

    // 1) t1 = x @ qU^T                     (16384, 32)
    sgemm_nt<32, 2><<<dim3(1, MM / 128), blk>>>(x, qU, nullptr, t1, MM, RR, EE);
    // 2) k  = x @ kW^T                     (16384, 64)
    sgemm_nt<64, 4><<<dim3(1, MM / 128), blk>>>(x, kW, nullptr, kk, MM, DD, EE);
    // 3) t2 = t1 @ qV^T                    (16384, 512)
    sgemm_nt<128, 8><<<dim3((EE / 2) / 128, MM / 128), blk>>>(t1, qV, nullptr, t2, MM, EE / 2, RR);
    // 4) q  = t2 @ qW^T + qb               (16384, 1024)
    sgemm_nt<128, 8><<<dim3(EE / 128, MM / 128), blk>>>(t2, qW, qb, q, MM, EE, EE / 2);
    // 5) kv fold                           (4, 256, 64)
    kv_kernel<<<dim3(KK / 4, BB), blk>>>(kk, kp, kv);
    // 6) fused attention                   (16384, 1024)
    attn_kernel<<<dim3(NN / 64, BB * HH), blk, ATTN_SMEM>>>(q, kv, attn);
    // 7) out = attn @ oW^T + ob            (16384, 1024)
    sgemm_nt<128, 8><<<dim3(EE / 128, MM / 128), blk>>>(attn, oW, ob, out, MM, EE, EE);
}

// round 10
// speedup vs baseline: 1.0042x; 1.0042x over previous
#include <cuda_runtime.h>
#include <cuda_bf16.h>

// Problem constants (fixed by the dataset)
#define BB   4
#define NN   4096
#define EE   1024
#define HH   16
#define DD   64
#define KK   256
#define RR   32
#define MM   (BB * NN)        // 16384 rows

// ---------------------------------------------------------------------------
// Scratch (device globals; no allocation allowed)
// ---------------------------------------------------------------------------
__device__ float g_t1[MM * RR];          // x @ qU^T           (16384, 32)
__device__ float g_k [MM * DD];          // x @ kW^T           (16384, 64)
__device__ float g_t2[MM * (EE / 2)];    // t1 @ qV^T          (16384, 512)
__device__ float g_q [MM * EE];          // t2 @ qW^T + qb     (16384, 1024)
__device__ float g_kv[BB * KK * DD];     // kv                 (4, 256, 64)
__device__ float g_at[MM * EE];          // attention output   (16384, 1024)

// ---------------------------------------------------------------------------
// Generic SGEMM (NT): C[M,N] = A[M,Kd] * B[N,Kd]^T (+ bias[n])
// BM=128, BK=8, TM=8; BN/TN templated (covers N = 32, 64, >=128).
// Requires: M % 128 == 0, N % BN == 0, Kd % 8 == 0 (true for all our shapes).
// ---------------------------------------------------------------------------
template<int BN, int TN>
__global__ __launch_bounds__(256)
void sgemm_nt(const float* __restrict__ A, const float* __restrict__ B,
              const float* __restrict__ bias, float* __restrict__ C,
              int M, int N, int Kd)
{
    constexpr int BM = 128, BK = 8, TM = 8;
    __shared__ float As[BK][BM];
    __shared__ float Bs[BK][BN];

    const int tid = threadIdx.x;
    const int ty  = tid >> 4;    // 0..15  -> rows ty*8..+8
    const int tx  = tid & 15;    // 0..15  -> cols tx*TN..+TN
    const int m0  = blockIdx.y * BM;
    const int n0  = blockIdx.x * BN;

    float acc[TM][TN];
#pragma unroll
    for (int i = 0; i < TM; i++)
#pragma unroll
        for (int j = 0; j < TN; j++) acc[i][j] = 0.f;

    const int nK = Kd / BK;
    for (int kt = 0; kt < nK; kt++) {
        const int k0 = kt * BK;
        // A tile: 128 rows x 8 k = 256 float4, one per thread (transposed store)
        {
            const int row = tid >> 1;
            const int kq  = (tid & 1) * 4;
            float4 v = *(const float4*)(A + (size_t)(m0 + row) * Kd + k0 + kq);
            As[kq + 0][row] = v.x; As[kq + 1][row] = v.y;
            As[kq + 2][row] = v.z; As[kq + 3][row] = v.w;
        }
        // B tile: BN rows x 8 k = BN*2 float4
        for (int i = tid; i < BN * 2; i += 256) {
            const int col = i >> 1;
            const int kq  = (i & 1) * 4;
            float4 v = *(const float4*)(B + (size_t)(n0 + col) * Kd + k0 + kq);
            Bs[kq + 0][col] = v.x; Bs[kq + 1][col] = v.y;
            Bs[kq + 2][col] = v.z; Bs[kq + 3][col] = v.w;
        }
        __syncthreads();

#pragma unroll
        for (int kk = 0; kk < BK; kk++) {
            float a[TM], b[TN];
#pragma unroll
            for (int i = 0; i < TM; i++) a[i] = As[kk][ty * TM + i];
#pragma unroll
            for (int j = 0; j < TN; j++) b[j] = Bs[kk][tx * TN + j];
#pragma unroll
            for (int i = 0; i < TM; i++)
#pragma unroll
                for (int j = 0; j < TN; j++)
                    acc[i][j] = fmaf(a[i], b[j], acc[i][j]);
        }
        __syncthreads();
    }

#pragma unroll
    for (int i = 0; i < TM; i++) {
        const int r = m0 + ty * TM + i;
#pragma unroll
        for (int j = 0; j < TN; j++) {
            const int c = n0 + tx * TN + j;
            float v = acc[i][j];
            if (bias) v += bias[c];
            C[(size_t)r * N + c] = v;
        }
    }
}

// ---------------------------------------------------------------------------
// kv[b,kidx,d] = sum_n  k[b,n,d] * key_proj[n,kidx]
// grid (KK/4, BB), block 256: 4 kidx per block, 64 d lanes each.
// ---------------------------------------------------------------------------
__global__ __launch_bounds__(256)
void kv_kernel(const float* __restrict__ kmat, const float* __restrict__ kp,
               float* __restrict__ kv)
{
    const int b    = blockIdx.y;
    const int kidx = blockIdx.x * 4 + (threadIdx.x >> 6);
    const int d    = threadIdx.x & 63;
    const float* kb = kmat + (size_t)b * NN * DD;

    float acc = 0.f;
#pragma unroll 4
    for (int n = 0; n < NN; n++)
        acc = fmaf(kb[n * DD + d], __ldg(&kp[n * KK + kidx]), acc);

    kv[((b << 8) + kidx) * DD + d] = acc;
}

// ---------------------------------------------------------------------------
// Fused attention: per block one (b,h) and a 64-row tile of n.
//   S = Q(64x64) @ KV^T (64x256)  [regs, 8x8/lane]
//   softmax over k (warp shuffles; each warp owns 8 rows, k = tx + 32j)
//   O = P(64x256) @ KV (64x64)    [P staged in smem]
// smem: KV[256][66] + Q[64][66] + P[64][260] = 151,040 B (dynamic).
// ---------------------------------------------------------------------------
#define LDK 66
#define LDP 260
#define ATTN_SMEM ((KK * LDK + 64 * LDK + 64 * LDP) * (int)sizeof(float))

__global__ __launch_bounds__(256, 1)
void attn_kernel(const float* __restrict__ q, const float* __restrict__ kv,
                 float* __restrict__ out)
{
    extern __shared__ float sm[];
    float* KVs = sm;                    // [256][66]
    float* Qs  = KVs + KK * LDK;        // [64][66]
    float* Ps  = Qs + 64 * LDK;         // [64][260]

    const int bh = blockIdx.y;
    const int b  = bh / HH;
    const int h  = bh % HH;
    const int n0 = blockIdx.x * 64;
    const int tid = threadIdx.x;

    // load KV[b] (256x64)
    for (int i = tid; i < KK * DD; i += 256) {
        const int k = i >> 6, d = i & 63;
        KVs[k * LDK + d] = kv[((b << 8) + k) * DD + d];
    }
    // load Q tile (64 rows x 64 d), head h
    for (int i = tid; i < 64 * DD; i += 256) {
        const int r = i >> 6, d = i & 63;
        Qs[r * LDK + d] = q[(size_t)(b * NN + n0 + r) * EE + h * DD + d];
    }
    __syncthreads();

    const int ty = tid >> 5;   // warp id: rows ty*8..+8
    const int tx = tid & 31;   // lane: k = tx + 32*j

    // ---- S = Q @ KV^T ----
    float acc[8][8];
#pragma unroll
    for (int i = 0; i < 8; i++)
#pragma unroll
        for (int j = 0; j < 8; j++) acc[i][j] = 0.f;

    for (int d = 0; d < DD; d++) {
        float qa[8], kb[8];
#pragma unroll
        for (int i = 0; i < 8; i++) qa[i] = Qs[(ty * 8 + i) * LDK + d];   // broadcast
#pragma unroll
        for (int j = 0; j < 8; j++) kb[j] = KVs[(tx + 32 * j) * LDK + d];
#pragma unroll
        for (int i = 0; i < 8; i++)
#pragma unroll
            for (int j = 0; j < 8; j++)
                acc[i][j] = fmaf(qa[i], kb[j], acc[i][j]);
    }

    // ---- softmax over k (scale = D^-0.5 = 0.125) ----
    const float scale = 0.125f;
#pragma unroll
    for (int i = 0; i < 8; i++) {
        float m = acc[i][0];
#pragma unroll
        for (int j = 1; j < 8; j++) m = fmaxf(m, acc[i][j]);
#pragma unroll
        for (int off = 16; off; off >>= 1)
            m = fmaxf(m, __shfl_xor_sync(0xffffffffu, m, off));
        float s = 0.f;
#pragma unroll
        for (int j = 0; j < 8; j++) {
            acc[i][j] = __expf((acc[i][j] - m) * scale);
            s += acc[i][j];
        }
#pragma unroll
        for (int off = 16; off; off >>= 1)
            s += __shfl_xor_sync(0xffffffffu, s, off);
        const float inv = __fdividef(1.f, s);
#pragma unroll
        for (int j = 0; j < 8; j++)
            Ps[(ty * 8 + i) * LDP + tx + 32 * j] = acc[i][j] * inv;
    }
    __syncthreads();

    // ---- O = P @ KV ---- (lane handles d = tx*2, tx*2+1)
    float o[8][2];
#pragma unroll
    for (int i = 0; i < 8; i++) { o[i][0] = 0.f; o[i][1] = 0.f; }

    for (int k = 0; k < KK; k++) {
        const float2 v = *(const float2*)&KVs[k * LDK + tx * 2];   // LDK even -> 8B aligned
#pragma unroll
        for (int i = 0; i < 8; i++) {
            const float p = Ps[(ty * 8 + i) * LDP + k];            // broadcast
            o[i][0] = fmaf(p, v.x, o[i][0]);
            o[i][1] = fmaf(p, v.y, o[i][1]);
        }
    }

#pragma unroll
    for (int i = 0; i < 8; i++) {
        const size_t base = (size_t)(b * NN + n0 + ty * 8 + i) * EE + h * DD + tx * 2;
        out[base + 0] = o[i][0];
        out[base + 1] = o[i][1];
    }
}

// ---------------------------------------------------------------------------
// Launch
// ---------------------------------------------------------------------------
extern "C" void kernel_launch(void* const* d_in, const int* in_sizes, int n_in,
                              void* d_out, int out_size)
{
    const float* x  = (const float*)d_in[0];
    const float* qU = (const float*)d_in[1];
    const float* qV = (const float*)d_in[2];
    const float* qW = (const float*)d_in[3];
    const float* qb = (const float*)d_in[4];
    const float* kW = (const float*)d_in[5];
    const float* kp = (const float*)d_in[6];
    const float* oW = (const float*)d_in[7];
    const float* ob = (const float*)d_in[8];
    float* out = (float*)d_out;

    float *t1, *kk, *t2, *q, *kv, *attn;
    cudaGetSymbolAddress((void**)&t1,   g_t1);
    cudaGetSymbolAddress((void**)&kk,   g_k);
    cudaGetSymbolAddress((void**)&t2,   g_t2);
    cudaGetSymbolAddress((void**)&q,    g_q);
    cudaGetSymbolAddress((void**)&kv,   g_kv);
    cudaGetSymbolAddress((void**)&attn, g_at);

    cudaFuncSetAttribute(attn_kernel,
                         cudaFuncAttributeMaxDynamicSharedMemorySize, ATTN_SMEM);

    const dim3 blk(256);

    // 1) t1 = x @ qU^T                     (16384, 32)
    sgemm_nt<32, 2><<<dim3(1, MM / 128), blk>>>(x, qU, nullptr, t1, MM, RR, EE);
    // 2) k  = x @ kW^T                     (16384, 64)
    sgemm_nt<64, 4><<<dim3(1, MM / 128), blk>>>(x, kW, nullptr, kk, MM, DD, EE);
    // 3) t2 = t1 @ qV^T                    (16384, 512)
    sgemm_nt<128, 8><<<dim3((EE / 2) / 128, MM / 128), blk>>>(t1, qV, nullptr, t2, MM, EE / 2, RR);
    // 4) q  = t2 @ qW^T + qb               (16384, 1024)
    sgemm_nt<128, 8><<<dim3(EE / 128, MM / 128), blk>>>(t2, qW, qb, q, MM, EE, EE / 2);
    // 5) kv fold                           (4, 256, 64)
    kv_kernel<<<dim3(KK / 4, BB), blk>>>(kk, kp, kv);
    // 6) fused attention                   (16384, 1024)
    attn_kernel<<<dim3(NN / 64, BB * HH), blk, ATTN_SMEM>>>(q, kv, attn);
    // 7) out = attn @ oW^T + ob            (16384, 1024)
    sgemm_nt<128, 8><<<dim3(EE / 128, MM / 128), blk>>>(attn, oW, ob, out, MM, EE, EE);
}

// round 11
// speedup vs baseline: 1.0062x; 1.0020x over previous
#include <cuda_runtime.h>
#include <cuda_bf16.h>

// Problem constants (fixed by the dataset)
#define BB   4
#define NN   4096
#define EE   1024
#define HH   16
#define DD   64
#define KK   256
#define RR   32
#define MM   (BB * NN)        // 16384 rows

// ---------------------------------------------------------------------------
// Scratch (device globals; no allocation allowed)
// ---------------------------------------------------------------------------
__device__ float g_t1[MM * RR];          // x @ qU^T           (16384, 32)
__device__ float g_k [MM * DD];          // x @ kW^T           (16384, 64)
__device__ float g_t2[MM * (EE / 2)];    // t1 @ qV^T          (16384, 512)
__device__ float g_q [MM * EE];          // t2 @ qW^T + qb     (16384, 1024)
__device__ float g_kv[BB * KK * DD];     // kv                 (4, 256, 64)
__device__ float g_at[MM * EE];          // attention output   (16384, 1024)

// ---------------------------------------------------------------------------
// Generic SGEMM (NT): C[M,N] = A[M,Kd] * B[N,Kd]^T (+ bias[n])
// BM=128, BK=8, TM=8; BN/TN templated (covers N = 32, 64, >=128).
// Requires: M % 128 == 0, N % BN == 0, Kd % 8 == 0 (true for all our shapes).
// ---------------------------------------------------------------------------
template<int BN, int TN>
__global__ __launch_bounds__(256)
void sgemm_nt(const float* __restrict__ A, const float* __restrict__ B,
              const float* __restrict__ bias, float* __restrict__ C,
              int M, int N, int Kd)
{
    constexpr int BM = 128, BK = 8, TM = 8;
    __shared__ float As[BK][BM];
    __shared__ float Bs[BK][BN];

    const int tid = threadIdx.x;
    const int ty  = tid >> 4;    // 0..15  -> rows ty*8..+8
    const int tx  = tid & 15;    // 0..15  -> cols tx*TN..+TN
    const int m0  = blockIdx.y * BM;
    const int n0  = blockIdx.x * BN;

    float acc[TM][TN];
#pragma unroll
    for (int i = 0; i < TM; i++)
#pragma unroll
        for (int j = 0; j < TN; j++) acc[i][j] = 0.f;

    const int nK = Kd / BK;
    for (int kt = 0; kt < nK; kt++) {
        const int k0 = kt * BK;
        // A tile: 128 rows x 8 k = 256 float4, one per thread (transposed store)
        {
            const int row = tid >> 1;
            const int kq  = (tid & 1) * 4;
            float4 v = *(const float4*)(A + (size_t)(m0 + row) * Kd + k0 + kq);
            As[kq + 0][row] = v.x; As[kq + 1][row] = v.y;
            As[kq + 2][row] = v.z; As[kq + 3][row] = v.w;
        }
        // B tile: BN rows x 8 k = BN*2 float4
        for (int i = tid; i < BN * 2; i += 256) {
            const int col = i >> 1;
            const int kq  = (i & 1) * 4;
            float4 v = *(const float4*)(B + (size_t)(n0 + col) * Kd + k0 + kq);
            Bs[kq + 0][col] = v.x; Bs[kq + 1][col] = v.y;
            Bs[kq + 2][col] = v.z; Bs[kq + 3][col] = v.w;
        }
        __syncthreads();

#pragma unroll
        for (int kk = 0; kk < BK; kk++) {
            float a[TM], b[TN];
#pragma unroll
            for (int i = 0; i < TM; i++) a[i] = As[kk][ty * TM + i];
#pragma unroll
            for (int j = 0; j < TN; j++) b[j] = Bs[kk][tx * TN + j];
#pragma unroll
            for (int i = 0; i < TM; i++)
#pragma unroll
                for (int j = 0; j < TN; j++)
                    acc[i][j] = fmaf(a[i], b[j], acc[i][j]);
        }
        __syncthreads();
    }

#pragma unroll
    for (int i = 0; i < TM; i++) {
        const int r = m0 + ty * TM + i;
#pragma unroll
        for (int j = 0; j < TN; j++) {
            const int c = n0 + tx * TN + j;
            float v = acc[i][j];
            if (bias) v += bias[c];
            C[(size_t)r * N + c] = v;
        }
    }
}

// ---------------------------------------------------------------------------
// kv[b,kidx,d] = sum_n  k[b,n,d] * key_proj[n,kidx]
// grid (KK/4, BB), block 256: 4 kidx per block, 64 d lanes each.
// ---------------------------------------------------------------------------
__global__ __launch_bounds__(256)
void kv_kernel(const float* __restrict__ kmat, const float* __restrict__ kp,
               float* __restrict__ kv)
{
    const int b    = blockIdx.y;
    const int kidx = blockIdx.x * 4 + (threadIdx.x >> 6);
    const int d    = threadIdx.x & 63;
    const float* kb = kmat + (size_t)b * NN * DD;

    float acc = 0.f;
#pragma unroll 4
    for (int n = 0; n < NN; n++)
        acc = fmaf(kb[n * DD + d], __ldg(&kp[n * KK + kidx]), acc);

    kv[((b << 8) + kidx) * DD + d] = acc;
}

// ---------------------------------------------------------------------------
// Fused attention: per block one (b,h) and a 64-row tile of n.
//   S = Q(64x64) @ KV^T (64x256)  [regs, 8x8/lane]
//   softmax over k (warp shuffles; each warp owns 8 rows, k = tx + 32j)
//   O = P(64x256) @ KV (64x64)    [P staged in smem]
// smem: KV[256][66] + Q[64][66] + P[64][260] = 151,040 B (dynamic).
// ---------------------------------------------------------------------------
#define LDK 66
#define LDP 260
#define ATTN_SMEM ((KK * LDK + 64 * LDK + 64 * LDP) * (int)sizeof(float))

__global__ __launch_bounds__(256, 1)
void attn_kernel(const float* __restrict__ q, const float* __restrict__ kv,
                 float* __restrict__ out)
{
    extern __shared__ float sm[];
    float* KVs = sm;                    // [256][66]
    float* Qs  = KVs + KK * LDK;        // [64][66]
    float* Ps  = Qs + 64 * LDK;         // [64][260]

    const int bh = blockIdx.y;
    const int b  = bh / HH;
    const int h  = bh % HH;
    const int n0 = blockIdx.x * 64;
    const int tid = threadIdx.x;

    // load KV[b] (256x64)
    for (int i = tid; i < KK * DD; i += 256) {
        const int k = i >> 6, d = i & 63;
        KVs[k * LDK + d] = kv[((b << 8) + k) * DD + d];
    }
    // load Q tile (64 rows x 64 d), head h
    for (int i = tid; i < 64 * DD; i += 256) {
        const int r = i >> 6, d = i & 63;
        Qs[r * LDK + d] = q[(size_t)(b * NN + n0 + r) * EE + h * DD + d];
    }
    __syncthreads();

    const int ty = tid >> 5;   // warp id: rows ty*8..+8
    const int tx = tid & 31;   // lane: k = tx + 32*j

    // ---- S = Q @ KV^T ----
    float acc[8][8];
#pragma unroll
    for (int i = 0; i < 8; i++)
#pragma unroll
        for (int j = 0; j < 8; j++) acc[i][j] = 0.f;

    for (int d = 0; d < DD; d++) {
        float qa[8], kb[8];
#pragma unroll
        for (int i = 0; i < 8; i++) qa[i] = Qs[(ty * 8 + i) * LDK + d];   // broadcast
#pragma unroll
        for (int j = 0; j < 8; j++) kb[j] = KVs[(tx + 32 * j) * LDK + d];
#pragma unroll
        for (int i = 0; i < 8; i++)
#pragma unroll
            for (int j = 0; j < 8; j++)
                acc[i][j] = fmaf(qa[i], kb[j], acc[i][j]);
    }

    // ---- softmax over k (scale = D^-0.5 = 0.125) ----
    const float scale = 0.125f;
#pragma unroll
    for (int i = 0; i < 8; i++) {
        float m = acc[i][0];
#pragma unroll
        for (int j = 1; j < 8; j++) m = fmaxf(m, acc[i][j]);
#pragma unroll
        for (int off = 16; off; off >>= 1)
            m = fmaxf(m, __shfl_xor_sync(0xffffffffu, m, off));
        float s = 0.f;
#pragma unroll
        for (int j = 0; j < 8; j++) {
            acc[i][j] = __expf((acc[i][j] - m) * scale);
            s += acc[i][j];
        }
#pragma unroll
        for (int off = 16; off; off >>= 1)
            s += __shfl_xor_sync(0xffffffffu, s, off);
        const float inv = __fdividef(1.f, s);
#pragma unroll
        for (int j = 0; j < 8; j++)
            Ps[(ty * 8 + i) * LDP + tx + 32 * j] = acc[i][j] * inv;
    }
    __syncthreads();

    // ---- O = P @ KV ---- (lane handles d = tx*2, tx*2+1)
    float o[8][2];
#pragma unroll
    for (int i = 0; i < 8; i++) { o[i][0] = 0.f; o[i][1] = 0.f; }

    for (int k = 0; k < KK; k++) {
        const float2 v = *(const float2*)&KVs[k * LDK + tx * 2];   // LDK even -> 8B aligned
#pragma unroll
        for (int i = 0; i < 8; i++) {
            const float p = Ps[(ty * 8 + i) * LDP + k];            // broadcast
            o[i][0] = fmaf(p, v.x, o[i][0]);
            o[i][1] = fmaf(p, v.y, o[i][1]);
        }
    }

#pragma unroll
    for (int i = 0; i < 8; i++) {
        const size_t base = (size_t)(b * NN + n0 + ty * 8 + i) * EE + h * DD + tx * 2;
        out[base + 0] = o[i][0];
        out[base + 1] = o[i][1];
    }
}

// ---------------------------------------------------------------------------
// Launch
// ---------------------------------------------------------------------------
extern "C" void kernel_launch(void* const* d_in, const int* in_sizes, int n_in,
                              void* d_out, int out_size)
{
    const float* x  = (const float*)d_in[0];
    const float* qU = (const float*)d_in[1];
    const float* qV = (const float*)d_in[2];
    const float* qW = (const float*)d_in[3];
    const float* qb = (const float*)d_in[4];
    const float* kW = (const float*)d_in[5];
    const float* kp = (const float*)d_in[6];
    const float* oW = (const float*)d_in[7];
    const float* ob = (const float*)d_in[8];
    float* out = (float*)d_out;

    float *t1, *kk, *t2, *q, *kv, *attn;
    cudaGetSymbolAddress((void**)&t1,   g_t1);
    cudaGetSymbolAddress((void**)&kk,   g_k);
    cudaGetSymbolAddress((void**)&t2,   g_t2);
    cudaGetSymbolAddress((void**)&q,    g_q);
    cudaGetSymbolAddress((void**)&kv,   g_kv);
    cudaGetSymbolAddress((void**)&attn, g_at);

    cudaFuncSetAttribute(attn_kernel,
                         cudaFuncAttributeMaxDynamicSharedMemorySize, ATTN_SMEM);

    const dim3 blk(256);

    // 1) t1 = x @ qU^T                     (16384, 32)
    sgemm_nt<32, 2><<<dim3(1, MM / 128), blk>>>(x, qU, nullptr, t1, MM, RR, EE);
    // 2) k  = x @ kW^T                     (16384, 64)
    sgemm_nt<64, 4><<<dim3(1, MM / 128), blk>>>(x, kW, nullptr, kk, MM, DD, EE);
    // 3) t2 = t1 @ qV^T                    (16384, 512)
    sgemm_nt<128, 8><<<dim3((EE / 2) / 128, MM / 128), blk>>>(t1, qV, nullptr, t2, MM, EE / 2, RR);
    // 4) q  = t2 @ qW^T + qb               (16384, 1024)
    sgemm_nt<128, 8><<<dim3(EE / 128, MM / 128), blk>>>(t2, qW, qb, q, MM, EE, EE / 2);
    // 5) kv fold                           (4, 256, 64)
    kv_kernel<<<dim3(KK / 4, BB), blk>>>(kk, kp, kv);
    // 6) fused attention                   (16384, 1024)
    attn_kernel<<<dim3(NN / 64, BB * HH), blk, ATTN_SMEM>>>(q, kv, attn);
    // 7) out = attn @ oW^T + ob            (16384, 1024)
    sgemm_nt<128, 8><<<dim3(EE / 128, MM / 128), blk>>>(attn, oW, ob, out, MM, EE, EE);
}

// round 12
// speedup vs baseline: 1.0069x; 1.0007x over previous
#include <cuda_runtime.h>
#include <cuda_bf16.h>

// Problem constants (fixed by the dataset)
#define BB   4
#define NN   4096
#define EE   1024
#define HH   16
#define DD   64
#define KK   256
#define RR   32
#define MM   (BB * NN)        // 16384 rows

// ---------------------------------------------------------------------------
// Scratch (device globals; no allocation allowed)
// ---------------------------------------------------------------------------
__device__ float g_t1[MM * RR];          // x @ qU^T           (16384, 32)
__device__ float g_k [MM * DD];          // x @ kW^T           (16384, 64)
__device__ float g_t2[MM * (EE / 2)];    // t1 @ qV^T          (16384, 512)
__device__ float g_q [MM * EE];          // t2 @ qW^T + qb     (16384, 1024)
__device__ float g_kv[BB * KK * DD];     // kv                 (4, 256, 64)
__device__ float g_at[MM * EE];          // attention output   (16384, 1024)

// ---------------------------------------------------------------------------
// Generic SGEMM (NT): C[M,N] = A[M,Kd] * B[N,Kd]^T (+ bias[n])
// BM=128, BK=8, TM=8; BN/TN templated (covers N = 32, 64, >=128).
// Requires: M % 128 == 0, N % BN == 0, Kd % 8 == 0 (true for all our shapes).
// ---------------------------------------------------------------------------
template<int BN, int TN>
__global__ __launch_bounds__(256)
void sgemm_nt(const float* __restrict__ A, const float* __restrict__ B,
              const float* __restrict__ bias, float* __restrict__ C,
              int M, int N, int Kd)
{
    constexpr int BM = 128, BK = 8, TM = 8;
    __shared__ float As[BK][BM];
    __shared__ float Bs[BK][BN];

    const int tid = threadIdx.x;
    const int ty  = tid >> 4;    // 0..15  -> rows ty*8..+8
    const int tx  = tid & 15;    // 0..15  -> cols tx*TN..+TN
    const int m0  = blockIdx.y * BM;
    const int n0  = blockIdx.x * BN;

    float acc[TM][TN];
#pragma unroll
    for (int i = 0; i < TM; i++)
#pragma unroll
        for (int j = 0; j < TN; j++) acc[i][j] = 0.f;

    const int nK = Kd / BK;
    for (int kt = 0; kt < nK; kt++) {
        const int k0 = kt * BK;
        // A tile: 128 rows x 8 k = 256 float4, one per thread (transposed store)
        {
            const int row = tid >> 1;
            const int kq  = (tid & 1) * 4;
            float4 v = *(const float4*)(A + (size_t)(m0 + row) * Kd + k0 + kq);
            As[kq + 0][row] = v.x; As[kq + 1][row] = v.y;
            As[kq + 2][row] = v.z; As[kq + 3][row] = v.w;
        }
        // B tile: BN rows x 8 k = BN*2 float4
        for (int i = tid; i < BN * 2; i += 256) {
            const int col = i >> 1;
            const int kq  = (i & 1) * 4;
            float4 v = *(const float4*)(B + (size_t)(n0 + col) * Kd + k0 + kq);
            Bs[kq + 0][col] = v.x; Bs[kq + 1][col] = v.y;
            Bs[kq + 2][col] = v.z; Bs[kq + 3][col] = v.w;
        }
        __syncthreads();

#pragma unroll
        for (int kk = 0; kk < BK; kk++) {
            float a[TM], b[TN];
#pragma unroll
            for (int i = 0; i < TM; i++) a[i] = As[kk][ty * TM + i];
#pragma unroll
            for (int j = 0; j < TN; j++) b[j] = Bs[kk][tx * TN + j];
#pragma unroll
            for (int i = 0; i < TM; i++)
#pragma unroll
                for (int j = 0; j < TN; j++)
                    acc[i][j] = fmaf(a[i], b[j], acc[i][j]);
        }
        __syncthreads();
    }

#pragma unroll
    for (int i = 0; i < TM; i++) {
        const int r = m0 + ty * TM + i;
#pragma unroll
        for (int j = 0; j < TN; j++) {
            const int c = n0 + tx * TN + j;
            float v = acc[i][j];
            if (bias) v += bias[c];
            C[(size_t)r * N + c] = v;
        }
    }
}

// ---------------------------------------------------------------------------
// kv[b,kidx,d] = sum_n  k[b,n,d] * key_proj[n,kidx]
// grid (KK/4, BB), block 256: 4 kidx per block, 64 d lanes each.
// ---------------------------------------------------------------------------
__global__ __launch_bounds__(256)
void kv_kernel(const float* __restrict__ kmat, const float* __restrict__ kp,
               float* __restrict__ kv)
{
    const int b    = blockIdx.y;
    const int kidx = blockIdx.x * 4 + (threadIdx.x >> 6);
    const int d    = threadIdx.x & 63;
    const float* kb = kmat + (size_t)b * NN * DD;

    float acc = 0.f;
#pragma unroll 4
    for (int n = 0; n < NN; n++)
        acc = fmaf(kb[n * DD + d], __ldg(&kp[n * KK + kidx]), acc);

    kv[((b << 8) + kidx) * DD + d] = acc;
}

// ---------------------------------------------------------------------------
// Fused attention: per block one (b,h) and a 64-row tile of n.
//   S = Q(64x64) @ KV^T (64x256)  [regs, 8x8/lane]
//   softmax over k (warp shuffles; each warp owns 8 rows, k = tx + 32j)
//   O = P(64x256) @ KV (64x64)    [P staged in smem]
// smem: KV[256][66] + Q[64][66] + P[64][260] = 151,040 B (dynamic).
// ---------------------------------------------------------------------------
#define LDK 66
#define LDP 260
#define ATTN_SMEM ((KK * LDK + 64 * LDK + 64 * LDP) * (int)sizeof(float))

__global__ __launch_bounds__(256, 1)
void attn_kernel(const float* __restrict__ q, const float* __restrict__ kv,
                 float* __restrict__ out)
{
    extern __shared__ float sm[];
    float* KVs = sm;                    // [256][66]
    float* Qs  = KVs + KK * LDK;        // [64][66]
    float* Ps  = Qs + 64 * LDK;         // [64][260]

    const int bh = blockIdx.y;
    const int b  = bh / HH;
    const int h  = bh % HH;
    const int n0 = blockIdx.x * 64;
    const int tid = threadIdx.x;

    // load KV[b] (256x64)
    for (int i = tid; i < KK * DD; i += 256) {
        const int k = i >> 6, d = i & 63;
        KVs[k * LDK + d] = kv[((b << 8) + k) * DD + d];
    }
    // load Q tile (64 rows x 64 d), head h
    for (int i = tid; i < 64 * DD; i += 256) {
        const int r = i >> 6, d = i & 63;
        Qs[r * LDK + d] = q[(size_t)(b * NN + n0 + r) * EE + h * DD + d];
    }
    __syncthreads();

    const int ty = tid >> 5;   // warp id: rows ty*8..+8
    const int tx = tid & 31;   // lane: k = tx + 32*j

    // ---- S = Q @ KV^T ----
    float acc[8][8];
#pragma unroll
    for (int i = 0; i < 8; i++)
#pragma unroll
        for (int j = 0; j < 8; j++) acc[i][j] = 0.f;

    for (int d = 0; d < DD; d++) {
        float qa[8], kb[8];
#pragma unroll
        for (int i = 0; i < 8; i++) qa[i] = Qs[(ty * 8 + i) * LDK + d];   // broadcast
#pragma unroll
        for (int j = 0; j < 8; j++) kb[j] = KVs[(tx + 32 * j) * LDK + d];
#pragma unroll
        for (int i = 0; i < 8; i++)
#pragma unroll
            for (int j = 0; j < 8; j++)
                acc[i][j] = fmaf(qa[i], kb[j], acc[i][j]);
    }

    // ---- softmax over k (scale = D^-0.5 = 0.125) ----
    const float scale = 0.125f;
#pragma unroll
    for (int i = 0; i < 8; i++) {
        float m = acc[i][0];
#pragma unroll
        for (int j = 1; j < 8; j++) m = fmaxf(m, acc[i][j]);
#pragma unroll
        for (int off = 16; off; off >>= 1)
            m = fmaxf(m, __shfl_xor_sync(0xffffffffu, m, off));
        float s = 0.f;
#pragma unroll
        for (int j = 0; j < 8; j++) {
            acc[i][j] = __expf((acc[i][j] - m) * scale);
            s += acc[i][j];
        }
#pragma unroll
        for (int off = 16; off; off >>= 1)
            s += __shfl_xor_sync(0xffffffffu, s, off);
        const float inv = __fdividef(1.f, s);
#pragma unroll
        for (int j = 0; j < 8; j++)
            Ps[(ty * 8 + i) * LDP + tx + 32 * j] = acc[i][j] * inv;
    }
    __syncthreads();

    // ---- O = P @ KV ---- (lane handles d = tx*2, tx*2+1)
    float o[8][2];
#pragma unroll
    for (int i = 0; i < 8; i++) { o[i][0] = 0.f; o[i][1] = 0.f; }

    for (int k = 0; k < KK; k++) {
        const float2 v = *(const float2*)&KVs[k * LDK + tx * 2];   // LDK even -> 8B aligned
#pragma unroll
        for (int i = 0; i < 8; i++) {
            const float p = Ps[(ty * 8 + i) * LDP + k];            // broadcast
            o[i][0] = fmaf(p, v.x, o[i][0]);
            o[i][1] = fmaf(p, v.y, o[i][1]);
        }
    }

#pragma unroll
    for (int i = 0; i < 8; i++) {
        const size_t base = (size_t)(b * NN + n0 + ty * 8 + i) * EE + h * DD + tx * 2;
        out[base + 0] = o[i][0];
        out[base + 1] = o[i][1];
    }
}

// ---------------------------------------------------------------------------
// Launch
// ---------------------------------------------------------------------------
extern "C" void kernel_launch(void* const* d_in, const int* in_sizes, int n_in,
                              void* d_out, int out_size)
{
    const float* x  = (const float*)d_in[0];
    const float* qU = (const float*)d_in[1];
    const float* qV = (const float*)d_in[2];
    const float* qW = (const float*)d_in[3];
    const float* qb = (const float*)d_in[4];
    const float* kW = (const float*)d_in[5];
    const float* kp = (const float*)d_in[6];
    const float* oW = (const float*)d_in[7];
    const float* ob = (const float*)d_in[8];
    float* out = (float*)d_out;

    float *t1, *kk, *t2, *q, *kv, *attn;
    cudaGetSymbolAddress((void**)&t1,   g_t1);
    cudaGetSymbolAddress((void**)&kk,   g_k);
    cudaGetSymbolAddress((void**)&t2,   g_t2);
    cudaGetSymbolAddress((void**)&q,    g_q);
    cudaGetSymbolAddress((void**)&kv,   g_kv);
    cudaGetSymbolAddress((void**)&attn, g_at);

    cudaFuncSetAttribute(attn_kernel,
                         cudaFuncAttributeMaxDynamicSharedMemorySize, ATTN_SMEM);

    const dim3 blk(256);

    // 1) t1 = x @ qU^T                     (16384, 32)
    sgemm_nt<32, 2><<<dim3(1, MM / 128), blk>>>(x, qU, nullptr, t1, MM, RR, EE);
    // 2) k  = x @ kW^T                     (16384, 64)
    sgemm_nt<64, 4><<<dim3(1, MM / 128), blk>>>(x, kW, nullptr, kk, MM, DD, EE);
    // 3) t2 = t1 @ qV^T                    (16384, 512)
    sgemm_nt<128, 8><<<dim3((EE / 2) / 128, MM / 128), blk>>>(t1, qV, nullptr, t2, MM, EE / 2, RR);
    // 4) q  = t2 @ qW^T + qb               (16384, 1024)
    sgemm_nt<128, 8><<<dim3(EE / 128, MM / 128), blk>>>(t2, qW, qb, q, MM, EE, EE / 2);
    // 5) kv fold                           (4, 256, 64)
    kv_kernel<<<dim3(KK / 4, BB), blk>>>(kk, kp, kv);
    // 6) fused attention                   (16384, 1024)
    attn_kernel<<<dim3(NN / 64, BB * HH), blk, ATTN_SMEM>>>(q, kv, attn);
    // 7) out = attn @ oW^T + ob            (16384, 1024)
    sgemm_nt<128, 8><<<dim3(EE / 128, MM / 128), blk>>>(attn, oW, ob, out, MM, EE, EE);
}